// round 2
// baseline (speedup 1.0000x reference)
#include <cuda_runtime.h>

#define T_  128
#define B_  2048
#define F_  128
#define H_  64
#define A_  15
#define TB_ (T_*B_)
#define G_  256   // 4*H gates

// Scratch (allocation-free rule: __device__ globals)
__device__ float g_gin[(size_t)TB_ * G_];   // precomputed input-gate preactivations
__device__ float g_z[(size_t)TB_ * H_];     // LSTM hidden outputs per step

// ---------------------------------------------------------------------------
// math helpers
// ---------------------------------------------------------------------------
__device__ __forceinline__ float fsig(float x) {
    return __fdividef(1.0f, 1.0f + __expf(-x));
}
__device__ __forceinline__ float ftanh_acc(float x) {
    x = fminf(15.0f, fmaxf(-15.0f, x));
    float e = __expf(-2.0f * x);
    return __fdividef(1.0f - e, 1.0f + e);
}
__device__ __forceinline__ float ftanh_fast(float x) {
    float y;
    asm("tanh.approx.f32 %0, %1;" : "=f"(y) : "f"(x));
    return y;
}
__device__ __forceinline__ unsigned tf32_rna(float x) {
    unsigned u; asm("cvt.rna.tf32.f32 %0, %1;" : "=r"(u) : "f"(x)); return u;
}
// d += a (m16k8, tf32) * b (k8n8, tf32)
__device__ __forceinline__ void mma8(float* d, const unsigned* a, unsigned b0, unsigned b1) {
    asm("mma.sync.aligned.m16n8k8.row.col.f32.tf32.tf32.f32 "
        "{%0,%1,%2,%3}, {%4,%5,%6,%7}, {%8,%9}, {%0,%1,%2,%3};"
        : "+f"(d[0]), "+f"(d[1]), "+f"(d[2]), "+f"(d[3])
        : "r"(a[0]), "r"(a[1]), "r"(a[2]), "r"(a[3]), "r"(b0), "r"(b1));
}
__device__ __forceinline__ void cp16(float* dst_smem, const float* src) {
    unsigned s = (unsigned)__cvta_generic_to_shared(dst_smem);
    asm volatile("cp.async.cg.shared.global [%0], [%1], 16;" :: "r"(s), "l"(src));
}

// ---------------------------------------------------------------------------
// Kernel 1: fused MLP encoder + input-gate GEMM via tf32 mma (3xtf32 accuracy).
// 128 threads (4 warps), 128 rows/block, 2048 blocks. Warp = m32 tile.
// smem regions (floats):
//   R0: xs [128][132]=16896         (later Wih_hi [64][260]=16640)
//   R1: W1 hi/lo [128][68]x2=17408  (later W2 hi/lo; later Wih_lo)
//   R2: h1 [128][68]=8704
//   R3: ys [128][68]=8704
//   R4: bias 384 (gin-bias 256 | b1 64 | b2 64)
// ---------------------------------------------------------------------------
#define XS_PAD 132
#define W_PAD  68
#define WG_PAD 260
#define ENC_R0 0
#define ENC_R1 16896
#define ENC_R2 (ENC_R1 + 17408)
#define ENC_R3 (ENC_R2 + 8704)
#define ENC_R4 (ENC_R3 + 8704)
#define ENC_SMEM (ENC_R4 + 384)          // 52096 floats = 208384 B

__global__ __launch_bounds__(128, 1)
void k_encode(const float* __restrict__ x,
              const float* __restrict__ W1, const float* __restrict__ b1,
              const float* __restrict__ W2, const float* __restrict__ b2,
              const float* __restrict__ Wih, const float* __restrict__ bih,
              const float* __restrict__ bhh) {
    extern __shared__ float sm[];
    float* xs   = sm + ENC_R0;
    float* wA   = sm + ENC_R1;     // stage weight hi
    float* h1   = sm + ENC_R2;
    float* ys   = sm + ENC_R3;
    float* bias = sm + ENC_R4;

    const int tid  = threadIdx.x;
    const int lane = tid & 31;
    const int w    = tid >> 5;
    const int row0 = blockIdx.x * 128;
    const int qr   = lane >> 2;    // 0..7
    const int qc   = lane & 3;     // 0..3

    // ---- loads: xs, W1 hi/lo, biases ----
    for (int i = tid; i < 128*F_; i += 128)
        xs[(i>>7)*XS_PAD + (i&127)] = x[(size_t)row0*F_ + i];
    for (int i = tid; i < F_*H_; i += 128) {
        int k = i >> 6, n = i & 63;
        float v = W1[i];
        float hi = __uint_as_float(tf32_rna(v));
        wA[k*W_PAD + n]        = hi;
        wA[8704 + k*W_PAD + n] = __uint_as_float(tf32_rna(v - hi));
    }
    for (int i = tid; i < G_; i += 128) bias[i] = bih[i] + bhh[i];
    for (int i = tid; i < H_;  i += 128) { bias[256+i] = b1[i]; bias[320+i] = b2[i]; }
    __syncthreads();

    // ================= S1: h1 = tanh(x @ W1 + b1), K=128 =================
    {
        float acc[2][8][4];
        #pragma unroll
        for (int mt = 0; mt < 2; mt++)
            #pragma unroll
            for (int nt = 0; nt < 8; nt++)
                #pragma unroll
                for (int j = 0; j < 4; j++) acc[mt][nt][j] = 0.f;

        float* wLo = wA + 8704;
        for (int kt = 0; kt < 16; kt++) {
            int k0 = kt * 8;
            unsigned ahi[2][4], alo[2][4];
            #pragma unroll
            for (int mt = 0; mt < 2; mt++) {
                int r = w*32 + mt*16 + qr;
                float a0 = xs[r*XS_PAD + k0 + qc];
                float a1 = xs[(r+8)*XS_PAD + k0 + qc];
                float a2 = xs[r*XS_PAD + k0 + qc + 4];
                float a3 = xs[(r+8)*XS_PAD + k0 + qc + 4];
                ahi[mt][0]=tf32_rna(a0); ahi[mt][1]=tf32_rna(a1);
                ahi[mt][2]=tf32_rna(a2); ahi[mt][3]=tf32_rna(a3);
                alo[mt][0]=tf32_rna(a0-__uint_as_float(ahi[mt][0]));
                alo[mt][1]=tf32_rna(a1-__uint_as_float(ahi[mt][1]));
                alo[mt][2]=tf32_rna(a2-__uint_as_float(ahi[mt][2]));
                alo[mt][3]=tf32_rna(a3-__uint_as_float(ahi[mt][3]));
            }
            #pragma unroll
            for (int nt = 0; nt < 8; nt++) {
                int bk = k0 + qc, bn = nt*8 + qr;
                unsigned bh0 = __float_as_uint(wA[bk*W_PAD + bn]);
                unsigned bh1 = __float_as_uint(wA[(bk+4)*W_PAD + bn]);
                unsigned bl0 = __float_as_uint(wLo[bk*W_PAD + bn]);
                unsigned bl1 = __float_as_uint(wLo[(bk+4)*W_PAD + bn]);
                #pragma unroll
                for (int mt = 0; mt < 2; mt++) {
                    mma8(acc[mt][nt], ahi[mt], bh0, bh1);
                    mma8(acc[mt][nt], alo[mt], bh0, bh1);
                    mma8(acc[mt][nt], ahi[mt], bl0, bl1);
                }
            }
        }
        #pragma unroll
        for (int mt = 0; mt < 2; mt++)
            #pragma unroll
            for (int nt = 0; nt < 8; nt++) {
                int r = w*32 + mt*16 + qr, c = nt*8 + 2*qc;
                float bb0 = bias[256+c], bb1 = bias[256+c+1];
                h1[r*W_PAD + c]       = ftanh_fast(acc[mt][nt][0] + bb0);
                h1[r*W_PAD + c + 1]   = ftanh_fast(acc[mt][nt][1] + bb1);
                h1[(r+8)*W_PAD + c]   = ftanh_fast(acc[mt][nt][2] + bb0);
                h1[(r+8)*W_PAD + c+1] = ftanh_fast(acc[mt][nt][3] + bb1);
            }
    }
    __syncthreads();
    // load W2 hi/lo into R1
    for (int i = tid; i < H_*H_; i += 128) {
        int k = i >> 6, n = i & 63;
        float v = W2[i];
        float hi = __uint_as_float(tf32_rna(v));
        wA[k*W_PAD + n]        = hi;
        wA[4352 + k*W_PAD + n] = __uint_as_float(tf32_rna(v - hi));
    }
    __syncthreads();

    // ================= S2: ys = tanh(h1 @ W2 + b2), K=64 =================
    {
        float acc[2][8][4];
        #pragma unroll
        for (int mt = 0; mt < 2; mt++)
            #pragma unroll
            for (int nt = 0; nt < 8; nt++)
                #pragma unroll
                for (int j = 0; j < 4; j++) acc[mt][nt][j] = 0.f;

        float* wLo = wA + 4352;
        for (int kt = 0; kt < 8; kt++) {
            int k0 = kt * 8;
            unsigned ahi[2][4], alo[2][4];
            #pragma unroll
            for (int mt = 0; mt < 2; mt++) {
                int r = w*32 + mt*16 + qr;
                float a0 = h1[r*W_PAD + k0 + qc];
                float a1 = h1[(r+8)*W_PAD + k0 + qc];
                float a2 = h1[r*W_PAD + k0 + qc + 4];
                float a3 = h1[(r+8)*W_PAD + k0 + qc + 4];
                ahi[mt][0]=tf32_rna(a0); ahi[mt][1]=tf32_rna(a1);
                ahi[mt][2]=tf32_rna(a2); ahi[mt][3]=tf32_rna(a3);
                alo[mt][0]=tf32_rna(a0-__uint_as_float(ahi[mt][0]));
                alo[mt][1]=tf32_rna(a1-__uint_as_float(ahi[mt][1]));
                alo[mt][2]=tf32_rna(a2-__uint_as_float(ahi[mt][2]));
                alo[mt][3]=tf32_rna(a3-__uint_as_float(ahi[mt][3]));
            }
            #pragma unroll
            for (int nt = 0; nt < 8; nt++) {
                int bk = k0 + qc, bn = nt*8 + qr;
                unsigned bh0 = __float_as_uint(wA[bk*W_PAD + bn]);
                unsigned bh1 = __float_as_uint(wA[(bk+4)*W_PAD + bn]);
                unsigned bl0 = __float_as_uint(wLo[bk*W_PAD + bn]);
                unsigned bl1 = __float_as_uint(wLo[(bk+4)*W_PAD + bn]);
                #pragma unroll
                for (int mt = 0; mt < 2; mt++) {
                    mma8(acc[mt][nt], ahi[mt], bh0, bh1);
                    mma8(acc[mt][nt], alo[mt], bh0, bh1);
                    mma8(acc[mt][nt], ahi[mt], bl0, bl1);
                }
            }
        }
        #pragma unroll
        for (int mt = 0; mt < 2; mt++)
            #pragma unroll
            for (int nt = 0; nt < 8; nt++) {
                int r = w*32 + mt*16 + qr, c = nt*8 + 2*qc;
                float bb0 = bias[320+c], bb1 = bias[320+c+1];
                ys[r*W_PAD + c]       = ftanh_fast(acc[mt][nt][0] + bb0);
                ys[r*W_PAD + c + 1]   = ftanh_fast(acc[mt][nt][1] + bb1);
                ys[(r+8)*W_PAD + c]   = ftanh_fast(acc[mt][nt][2] + bb0);
                ys[(r+8)*W_PAD + c+1] = ftanh_fast(acc[mt][nt][3] + bb1);
            }
    }
    __syncthreads();
    // load Wih (transposed to [k][n]) hi -> R0, lo -> R1
    {
        float* wgh = sm + ENC_R0;
        float* wgl = sm + ENC_R1;
        const int kk = tid & 63;
        const int nh = tid >> 6;         // 0 or 1
        for (int it = 0; it < 128; it++) {
            int n = it*2 + nh;
            float v = Wih[n*H_ + kk];
            float hi = __uint_as_float(tf32_rna(v));
            wgh[kk*WG_PAD + n] = hi;
            wgl[kk*WG_PAD + n] = __uint_as_float(tf32_rna(v - hi));
        }
    }
    __syncthreads();

    // ================= S3: gin = ys @ Wih^T + bias, K=64, N=256 ==========
    {
        float* wgh = sm + ENC_R0;
        float* wgl = sm + ENC_R1;
        for (int ch = 0; ch < 4; ch++) {
            float acc[2][8][4];
            #pragma unroll
            for (int mt = 0; mt < 2; mt++)
                #pragma unroll
                for (int nt = 0; nt < 8; nt++)
                    #pragma unroll
                    for (int j = 0; j < 4; j++) acc[mt][nt][j] = 0.f;

            for (int kt = 0; kt < 8; kt++) {
                int k0 = kt * 8;
                unsigned ahi[2][4], alo[2][4];
                #pragma unroll
                for (int mt = 0; mt < 2; mt++) {
                    int r = w*32 + mt*16 + qr;
                    float a0 = ys[r*W_PAD + k0 + qc];
                    float a1 = ys[(r+8)*W_PAD + k0 + qc];
                    float a2 = ys[r*W_PAD + k0 + qc + 4];
                    float a3 = ys[(r+8)*W_PAD + k0 + qc + 4];
                    ahi[mt][0]=tf32_rna(a0); ahi[mt][1]=tf32_rna(a1);
                    ahi[mt][2]=tf32_rna(a2); ahi[mt][3]=tf32_rna(a3);
                    alo[mt][0]=tf32_rna(a0-__uint_as_float(ahi[mt][0]));
                    alo[mt][1]=tf32_rna(a1-__uint_as_float(ahi[mt][1]));
                    alo[mt][2]=tf32_rna(a2-__uint_as_float(ahi[mt][2]));
                    alo[mt][3]=tf32_rna(a3-__uint_as_float(ahi[mt][3]));
                }
                #pragma unroll
                for (int nt = 0; nt < 8; nt++) {
                    int bk = k0 + qc, bn = ch*64 + nt*8 + qr;
                    unsigned bh0 = __float_as_uint(wgh[bk*WG_PAD + bn]);
                    unsigned bh1 = __float_as_uint(wgh[(bk+4)*WG_PAD + bn]);
                    unsigned bl0 = __float_as_uint(wgl[bk*WG_PAD + bn]);
                    unsigned bl1 = __float_as_uint(wgl[(bk+4)*WG_PAD + bn]);
                    #pragma unroll
                    for (int mt = 0; mt < 2; mt++) {
                        mma8(acc[mt][nt], ahi[mt], bh0, bh1);
                        mma8(acc[mt][nt], alo[mt], bh0, bh1);
                        mma8(acc[mt][nt], ahi[mt], bl0, bl1);
                    }
                }
            }
            #pragma unroll
            for (int mt = 0; mt < 2; mt++)
                #pragma unroll
                for (int nt = 0; nt < 8; nt++) {
                    int r = row0 + w*32 + mt*16 + qr;
                    int c = ch*64 + nt*8 + 2*qc;
                    float bb0 = bias[c], bb1 = bias[c+1];
                    *(float2*)&g_gin[(size_t)r*G_ + c] =
                        make_float2(acc[mt][nt][0] + bb0, acc[mt][nt][1] + bb1);
                    *(float2*)&g_gin[(size_t)(r+8)*G_ + c] =
                        make_float2(acc[mt][nt][2] + bb0, acc[mt][nt][3] + bb1);
                }
        }
    }
}

// ---------------------------------------------------------------------------
// Kernel 2: LSTM recurrence via tf32 mma. 16 batch rows/block, 128 blocks,
// 128 threads. Whh fragments register-resident (2-term tf32: Ahi*B + Alo*B).
// gin double-buffered via cp.async. Cell update in accurate fp32.
// smem (floats): hsh 16*68 | gs 16*264 | ginb 2*4096 | done_s 2048
// ---------------------------------------------------------------------------
#define LS_HP 68
#define LS_GP 264
#define LS_HSH  0
#define LS_GS   (16*LS_HP)                 // 1088
#define LS_GINB (LS_GS + 16*LS_GP)         // 5312
#define LS_DONE (LS_GINB + 2*16*G_)        // 13504
#define LS_SMEM (LS_DONE + T_*16)          // 15552 floats = 62208 B

__global__ __launch_bounds__(128, 1)
void k_lstm(const float* __restrict__ done,
            const float* __restrict__ h0, const float* __restrict__ c0,
            const float* __restrict__ Whh, float* __restrict__ out) {
    extern __shared__ float sm[];
    float* hsh    = sm + LS_HSH;
    float* gs     = sm + LS_GS;
    float* ginb   = sm + LS_GINB;
    float* done_s = sm + LS_DONE;

    const int tid  = threadIdx.x;
    const int lane = tid & 31;
    const int w    = tid >> 5;
    const int b0   = blockIdx.x * 16;
    const int qr   = lane >> 2, qc = lane & 3;

    // Whh fragments in registers: warp w owns gate cols [w*64, w*64+64)
    unsigned bf0[8][8], bf1[8][8];
    #pragma unroll
    for (int kt = 0; kt < 8; kt++)
        #pragma unroll
        for (int nt = 0; nt < 8; nt++) {
            int n = w*64 + nt*8 + qr, k = kt*8 + qc;
            bf0[kt][nt] = tf32_rna(Whh[n*H_ + k]);
            bf1[kt][nt] = tf32_rna(Whh[n*H_ + k + 4]);
        }

    for (int i = tid; i < T_*16; i += 128)
        done_s[i] = done[(i>>4)*B_ + b0 + (i&15)];

    const int rC = tid >> 3, u0 = (tid & 7) * 8;
    float c_reg[8];
    #pragma unroll
    for (int i = 0; i < 8; i++) {
        c_reg[i] = c0[(b0 + rC)*H_ + u0 + i];
        hsh[rC*LS_HP + u0 + i] = h0[(b0 + rC)*H_ + u0 + i];
    }

    // prologue: prefetch gin[t=0]
    {
        const float* src = g_gin + (size_t)b0 * G_;
        #pragma unroll
        for (int j = 0; j < 8; j++) {
            int q = tid + j*128;
            cp16(ginb + q*4, src + q*4);
        }
        asm volatile("cp.async.commit_group;");
    }
    __syncthreads();

    for (int t = 0; t < T_; t++) {
        // done-mask own slice
        float m = 1.0f - done_s[t*16 + rC];
        #pragma unroll
        for (int i = 0; i < 8; i++) c_reg[i] *= m;
        #pragma unroll
        for (int i = 0; i < 8; i++) hsh[rC*LS_HP + u0 + i] *= m;
        __syncthreads();

        // prefetch gin[t+1] (safe: all threads finished reading this buffer)
        if (t + 1 < T_) {
            float* dst = ginb + ((t+1)&1) * (16*G_);
            const float* src = g_gin + (size_t)((t+1)*B_ + b0) * G_;
            #pragma unroll
            for (int j = 0; j < 8; j++) {
                int q = tid + j*128;
                cp16(dst + q*4, src + q*4);
            }
            asm volatile("cp.async.commit_group;");
        }

        // gates_rec = h @ Whh^T  (m16 x n64 per warp)
        float acc[8][4];
        #pragma unroll
        for (int nt = 0; nt < 8; nt++)
            #pragma unroll
            for (int j = 0; j < 4; j++) acc[nt][j] = 0.f;

        #pragma unroll
        for (int kt = 0; kt < 8; kt++) {
            int k0 = kt*8;
            float a0 = hsh[qr*LS_HP + k0 + qc];
            float a1 = hsh[(qr+8)*LS_HP + k0 + qc];
            float a2 = hsh[qr*LS_HP + k0 + qc + 4];
            float a3 = hsh[(qr+8)*LS_HP + k0 + qc + 4];
            unsigned ahi[4], alo[4];
            ahi[0]=tf32_rna(a0); ahi[1]=tf32_rna(a1);
            ahi[2]=tf32_rna(a2); ahi[3]=tf32_rna(a3);
            alo[0]=tf32_rna(a0-__uint_as_float(ahi[0]));
            alo[1]=tf32_rna(a1-__uint_as_float(ahi[1]));
            alo[2]=tf32_rna(a2-__uint_as_float(ahi[2]));
            alo[3]=tf32_rna(a3-__uint_as_float(ahi[3]));
            #pragma unroll
            for (int nt = 0; nt < 8; nt++) {
                mma8(acc[nt], ahi, bf0[kt][nt], bf1[kt][nt]);
                mma8(acc[nt], alo, bf0[kt][nt], bf1[kt][nt]);
            }
        }
        #pragma unroll
        for (int nt = 0; nt < 8; nt++) {
            int c = w*64 + nt*8 + 2*qc;
            *(float2*)&gs[qr*LS_GP + c]     = make_float2(acc[nt][0], acc[nt][1]);
            *(float2*)&gs[(qr+8)*LS_GP + c] = make_float2(acc[nt][2], acc[nt][3]);
        }

        if (t + 1 < T_) asm volatile("cp.async.wait_group 1;");
        else            asm volatile("cp.async.wait_group 0;");
        __syncthreads();

        // cell update (gate order i,f,g,o), accurate transcendentals
        const float* gv = ginb + (t&1)*(16*G_) + rC*G_;
        float hn[8];
        #pragma unroll
        for (int i = 0; i < 8; i++) {
            int u = u0 + i;
            float gi = gs[rC*LS_GP + u]        + gv[u];
            float gf = gs[rC*LS_GP + 64 + u]   + gv[64 + u];
            float gc = gs[rC*LS_GP + 128 + u]  + gv[128 + u];
            float go = gs[rC*LS_GP + 192 + u]  + gv[192 + u];
            float cn = fsig(gf)*c_reg[i] + fsig(gi)*ftanh_acc(gc);
            c_reg[i] = cn;
            hn[i] = fsig(go)*ftanh_acc(cn);
            hsh[rC*LS_HP + u] = hn[i];
        }
        float* zp = g_z + (size_t)(t*B_ + b0 + rC)*H_ + u0;
        ((float4*)zp)[0] = make_float4(hn[0], hn[1], hn[2], hn[3]);
        ((float4*)zp)[1] = make_float4(hn[4], hn[5], hn[6], hn[7]);
    }

    // epilogue: hT, cT (layout: logits | vf | hT | cT)
    const size_t OH = (size_t)TB_ * 16;
    #pragma unroll
    for (int i = 0; i < 8; i++) {
        out[OH + (size_t)(b0 + rC)*H_ + u0 + i]                 = hsh[rC*LS_HP + u0 + i];
        out[OH + (size_t)B_*H_ + (size_t)(b0 + rC)*H_ + u0 + i] = c_reg[i];
    }
}

// ---------------------------------------------------------------------------
// Kernel 3: actor/critic heads (unchanged from R1 — already cheap).
// ---------------------------------------------------------------------------
__global__ __launch_bounds__(128)
void k_heads(const float* __restrict__ Wa, const float* __restrict__ ba,
             const float* __restrict__ Wc, const float* __restrict__ bc,
             float* __restrict__ out) {
    __shared__ float ws[H_*16];
    __shared__ float zs[128*65];
    const int tid  = threadIdx.x;
    const int row0 = blockIdx.x * 128;

    for (int i = tid; i < 128*H_; i += 128) zs[(i>>6)*65 + (i&63)] = g_z[(size_t)row0*H_ + i];
    for (int i = tid; i < H_*16; i += 128) {
        int k = i >> 4, j = i & 15;
        ws[i] = (j < 15) ? Wa[k*A_ + j] : Wc[k];
    }
    __syncthreads();

    float acc[16];
    #pragma unroll
    for (int j = 0; j < 15; j++) acc[j] = ba[j];
    acc[15] = bc[0];
    #pragma unroll 4
    for (int k = 0; k < H_; k++) {
        float a = zs[tid*65 + k];
        #pragma unroll
        for (int j = 0; j < 16; j++) acc[j] = fmaf(a, ws[k*16 + j], acc[j]);
    }
    const size_t r = (size_t)row0 + tid;
    #pragma unroll
    for (int j = 0; j < 15; j++) out[r*A_ + j] = acc[j];
    out[(size_t)TB_*A_ + r] = acc[15];
}

// ---------------------------------------------------------------------------
extern "C" void kernel_launch(void* const* d_in, const int* in_sizes, int n_in,
                              void* d_out, int out_size) {
    const float* x    = (const float*)d_in[0];
    const float* done = (const float*)d_in[1];
    const float* h0   = (const float*)d_in[2];
    const float* c0   = (const float*)d_in[3];
    const float* W1   = (const float*)d_in[4];
    const float* b1   = (const float*)d_in[5];
    const float* W2   = (const float*)d_in[6];
    const float* b2   = (const float*)d_in[7];
    const float* Wih  = (const float*)d_in[8];
    const float* bih  = (const float*)d_in[9];
    const float* Whh  = (const float*)d_in[10];
    const float* bhh  = (const float*)d_in[11];
    const float* Wa   = (const float*)d_in[12];
    const float* ba   = (const float*)d_in[13];
    const float* Wc   = (const float*)d_in[14];
    const float* bc   = (const float*)d_in[15];
    float* out = (float*)d_out;

    cudaFuncSetAttribute(k_encode, cudaFuncAttributeMaxDynamicSharedMemorySize, ENC_SMEM*4);
    cudaFuncSetAttribute(k_lstm,   cudaFuncAttributeMaxDynamicSharedMemorySize, LS_SMEM*4);

    k_encode<<<TB_/128, 128, ENC_SMEM*4>>>(x, W1, b1, W2, b2, Wih, bih, bhh);
    k_lstm<<<B_/16, 128, LS_SMEM*4>>>(done, h0, c0, Whh, out);
    k_heads<<<TB_/128, 128>>>(Wa, ba, Wc, bc, out);
}

// round 4
// speedup vs baseline: 2.4794x; 2.4794x over previous
#include <cuda_runtime.h>

#define T_  128
#define B_  2048
#define F_  128
#define H_  64
#define A_  15
#define TB_ (T_*B_)
#define G_  256   // 4*H gates

// Scratch (allocation-free rule: __device__ globals)
__device__ float g_gin[(size_t)TB_ * G_];   // precomputed input-gate preactivations
__device__ float g_z[(size_t)TB_ * H_];     // LSTM hidden outputs per step

// ---------------------------------------------------------------------------
// math helpers
// ---------------------------------------------------------------------------
__device__ __forceinline__ float fsig(float x) {
    return __fdividef(1.0f, 1.0f + __expf(-x));
}
__device__ __forceinline__ float ftanh_fast(float x) {
    float y;
    asm("tanh.approx.f32 %0, %1;" : "=f"(y) : "f"(x));
    return y;
}
__device__ __forceinline__ unsigned tf32_rna(float x) {
    unsigned u; asm("cvt.rna.tf32.f32 %0, %1;" : "=r"(u) : "f"(x)); return u;
}
__device__ __forceinline__ float tf32f(float x) {
    return __uint_as_float(tf32_rna(x));
}
// d += a (m16k8, tf32) * b (k8n8, tf32)
__device__ __forceinline__ void mma8(float* d, const unsigned* a, unsigned b0, unsigned b1) {
    asm("mma.sync.aligned.m16n8k8.row.col.f32.tf32.tf32.f32 "
        "{%0,%1,%2,%3}, {%4,%5,%6,%7}, {%8,%9}, {%0,%1,%2,%3};"
        : "+f"(d[0]), "+f"(d[1]), "+f"(d[2]), "+f"(d[3])
        : "r"(a[0]), "r"(a[1]), "r"(a[2]), "r"(a[3]), "r"(b0), "r"(b1));
}
__device__ __forceinline__ void cp16(float* dst_smem, const float* src) {
    unsigned s = (unsigned)__cvta_generic_to_shared(dst_smem);
    asm volatile("cp.async.cg.shared.global [%0], [%1], 16;" :: "r"(s), "l"(src));
}

// ---------------------------------------------------------------------------
// Kernel 1: fused MLP encoder + input-gate GEMM via tf32 mma (2-term:
// A split hi/lo, B rounded once). 256 threads (8 warps), 128 rows/block.
// smem (floats):
//   R0: xs [128][132] (16896) -> later Wih raw fp32 [256][68] (17408)
//   R1: W1 tf32 [128][72] (9216) -> later W2 tf32 [64][72]
//   R2: h1 [128][68] (8704)
//   R3: ys [128][68] (8704)
//   R4: bias 384 (gin-bias 256 | b1 64 | b2 64)
// total 44416 floats = 177664 B  (1 block/SM, 8 warps)
// ---------------------------------------------------------------------------
#define XS_PAD 132
#define W_PAD  72
#define WG_PAD 68
#define ENC_R0 0
#define ENC_R1 17408
#define ENC_R2 (ENC_R1 + 9216)
#define ENC_R3 (ENC_R2 + 8704)
#define ENC_R4 (ENC_R3 + 8704)
#define ENC_SMEM (ENC_R4 + 384)

__global__ __launch_bounds__(256, 1)
void k_encode(const float* __restrict__ x,
              const float* __restrict__ W1, const float* __restrict__ b1,
              const float* __restrict__ W2, const float* __restrict__ b2,
              const float* __restrict__ Wih, const float* __restrict__ bih,
              const float* __restrict__ bhh) {
    extern __shared__ float sm[];
    float* xs   = sm + ENC_R0;     // [128][132]
    float* wg   = sm + ENC_R0;     // later: Wih raw [256][68]
    float* wA   = sm + ENC_R1;     // W1/W2 tf32-rounded
    float* h1   = sm + ENC_R2;
    float* ys   = sm + ENC_R3;
    float* bias = sm + ENC_R4;

    const int tid  = threadIdx.x;
    const int lane = tid & 31;
    const int w    = tid >> 5;
    const int row0 = blockIdx.x * 128;
    const int qr   = lane >> 2;    // 0..7
    const int qc   = lane & 3;     // 0..3
    const int m0   = w * 16;       // warp's row tile

    // ---- async load xs; load W1 (tf32-rounded) and biases ----
    #pragma unroll
    for (int j = 0; j < 16; j++) {
        int idx = (tid + j*256) * 4;          // 0..16383
        int r = idx >> 7, c = idx & 127;
        cp16(xs + r*XS_PAD + c, x + (size_t)row0*F_ + idx);
    }
    asm volatile("cp.async.commit_group;");
    for (int i = tid; i < F_*H_; i += 256) {
        int k = i >> 6, n = i & 63;
        wA[k*W_PAD + n] = tf32f(W1[i]);
    }
    for (int i = tid; i < G_; i += 256) bias[i] = bih[i] + bhh[i];
    for (int i = tid; i < H_;  i += 256) { bias[256+i] = b1[i]; bias[320+i] = b2[i]; }
    asm volatile("cp.async.wait_group 0;");
    __syncthreads();

    // ================= S1: h1 = tanh(x @ W1 + b1), K=128 =================
    {
        float acc[8][4];
        #pragma unroll
        for (int nt = 0; nt < 8; nt++)
            #pragma unroll
            for (int j = 0; j < 4; j++) acc[nt][j] = 0.f;

        #pragma unroll 4
        for (int kt = 0; kt < 16; kt++) {
            int k0 = kt * 8;
            float a0 = xs[(m0+qr)*XS_PAD + k0 + qc];
            float a1 = xs[(m0+qr+8)*XS_PAD + k0 + qc];
            float a2 = xs[(m0+qr)*XS_PAD + k0 + qc + 4];
            float a3 = xs[(m0+qr+8)*XS_PAD + k0 + qc + 4];
            unsigned ahi[4], alo[4];
            ahi[0]=tf32_rna(a0); ahi[1]=tf32_rna(a1);
            ahi[2]=tf32_rna(a2); ahi[3]=tf32_rna(a3);
            alo[0]=tf32_rna(a0-__uint_as_float(ahi[0]));
            alo[1]=tf32_rna(a1-__uint_as_float(ahi[1]));
            alo[2]=tf32_rna(a2-__uint_as_float(ahi[2]));
            alo[3]=tf32_rna(a3-__uint_as_float(ahi[3]));
            #pragma unroll
            for (int nt = 0; nt < 8; nt++) {
                int bk = k0 + qc, bn = nt*8 + qr;
                unsigned bh0 = __float_as_uint(wA[bk*W_PAD + bn]);
                unsigned bh1 = __float_as_uint(wA[(bk+4)*W_PAD + bn]);
                mma8(acc[nt], ahi, bh0, bh1);
                mma8(acc[nt], alo, bh0, bh1);
            }
        }
        #pragma unroll
        for (int nt = 0; nt < 8; nt++) {
            int c = nt*8 + 2*qc;
            float bb0 = bias[256+c], bb1 = bias[256+c+1];
            *(float2*)&h1[(m0+qr)*WG_PAD + c] =
                make_float2(ftanh_fast(acc[nt][0]+bb0), ftanh_fast(acc[nt][1]+bb1));
            *(float2*)&h1[(m0+qr+8)*WG_PAD + c] =
                make_float2(ftanh_fast(acc[nt][2]+bb0), ftanh_fast(acc[nt][3]+bb1));
        }
    }
    __syncthreads();

    // xs region dead: async-load Wih raw fp32 [256][68] (FULL 256x64); W2 tf32.
    #pragma unroll
    for (int j = 0; j < 16; j++) {
        int r = tid + j*256;                  // 0..4095
        int n = r >> 4;                       // 0..255
        int c = (r & 15) * 4;                 // 0..60
        cp16(wg + n*WG_PAD + c, Wih + n*H_ + c);
    }
    asm volatile("cp.async.commit_group;");
    for (int i = tid; i < H_*H_; i += 256) {
        int k = i >> 6, n = i & 63;
        wA[k*W_PAD + n] = tf32f(W2[i]);
    }
    __syncthreads();

    // ================= S2: ys = tanh(h1 @ W2 + b2), K=64 =================
    {
        float acc[8][4];
        #pragma unroll
        for (int nt = 0; nt < 8; nt++)
            #pragma unroll
            for (int j = 0; j < 4; j++) acc[nt][j] = 0.f;

        #pragma unroll 2
        for (int kt = 0; kt < 8; kt++) {
            int k0 = kt * 8;
            float a0 = h1[(m0+qr)*WG_PAD + k0 + qc];
            float a1 = h1[(m0+qr+8)*WG_PAD + k0 + qc];
            float a2 = h1[(m0+qr)*WG_PAD + k0 + qc + 4];
            float a3 = h1[(m0+qr+8)*WG_PAD + k0 + qc + 4];
            unsigned ahi[4], alo[4];
            ahi[0]=tf32_rna(a0); ahi[1]=tf32_rna(a1);
            ahi[2]=tf32_rna(a2); ahi[3]=tf32_rna(a3);
            alo[0]=tf32_rna(a0-__uint_as_float(ahi[0]));
            alo[1]=tf32_rna(a1-__uint_as_float(ahi[1]));
            alo[2]=tf32_rna(a2-__uint_as_float(ahi[2]));
            alo[3]=tf32_rna(a3-__uint_as_float(ahi[3]));
            #pragma unroll
            for (int nt = 0; nt < 8; nt++) {
                int bk = k0 + qc, bn = nt*8 + qr;
                unsigned bh0 = __float_as_uint(wA[bk*W_PAD + bn]);
                unsigned bh1 = __float_as_uint(wA[(bk+4)*W_PAD + bn]);
                mma8(acc[nt], ahi, bh0, bh1);
                mma8(acc[nt], alo, bh0, bh1);
            }
        }
        #pragma unroll
        for (int nt = 0; nt < 8; nt++) {
            int c = nt*8 + 2*qc;
            float bb0 = bias[320+c], bb1 = bias[320+c+1];
            *(float2*)&ys[(m0+qr)*WG_PAD + c] =
                make_float2(ftanh_fast(acc[nt][0]+bb0), ftanh_fast(acc[nt][1]+bb1));
            *(float2*)&ys[(m0+qr+8)*WG_PAD + c] =
                make_float2(ftanh_fast(acc[nt][2]+bb0), ftanh_fast(acc[nt][3]+bb1));
        }
    }
    asm volatile("cp.async.wait_group 0;");
    __syncthreads();

    // ===== S3: gin = ys @ Wih^T + bias, K=64, N=256 (B = Wih[n][k] raw) =====
    for (int ch = 0; ch < 4; ch++) {
        float acc[8][4];
        #pragma unroll
        for (int nt = 0; nt < 8; nt++)
            #pragma unroll
            for (int j = 0; j < 4; j++) acc[nt][j] = 0.f;

        #pragma unroll 2
        for (int kt = 0; kt < 8; kt++) {
            int k0 = kt * 8;
            float a0 = ys[(m0+qr)*WG_PAD + k0 + qc];
            float a1 = ys[(m0+qr+8)*WG_PAD + k0 + qc];
            float a2 = ys[(m0+qr)*WG_PAD + k0 + qc + 4];
            float a3 = ys[(m0+qr+8)*WG_PAD + k0 + qc + 4];
            unsigned ahi[4], alo[4];
            ahi[0]=tf32_rna(a0); ahi[1]=tf32_rna(a1);
            ahi[2]=tf32_rna(a2); ahi[3]=tf32_rna(a3);
            alo[0]=tf32_rna(a0-__uint_as_float(ahi[0]));
            alo[1]=tf32_rna(a1-__uint_as_float(ahi[1]));
            alo[2]=tf32_rna(a2-__uint_as_float(ahi[2]));
            alo[3]=tf32_rna(a3-__uint_as_float(ahi[3]));
            #pragma unroll
            for (int nt = 0; nt < 8; nt++) {
                int bn = ch*64 + nt*8 + qr, bk = k0 + qc;
                unsigned bh0 = tf32_rna(wg[bn*WG_PAD + bk]);
                unsigned bh1 = tf32_rna(wg[bn*WG_PAD + bk + 4]);
                mma8(acc[nt], ahi, bh0, bh1);
                mma8(acc[nt], alo, bh0, bh1);
            }
        }
        #pragma unroll
        for (int nt = 0; nt < 8; nt++) {
            int r = row0 + m0 + qr;
            int c = ch*64 + nt*8 + 2*qc;
            float bb0 = bias[c], bb1 = bias[c+1];
            *(float2*)&g_gin[(size_t)r*G_ + c] =
                make_float2(acc[nt][0] + bb0, acc[nt][1] + bb1);
            *(float2*)&g_gin[(size_t)(r+8)*G_ + c] =
                make_float2(acc[nt][2] + bb0, acc[nt][3] + bb1);
        }
    }
}

// ---------------------------------------------------------------------------
// Kernel 2: LSTM recurrence via tf32 mma (1-term: h rounded to tf32 — h is
// in [-1,1], rounding error ~1e-4, negligible vs gates O(1)).
// 16 batch rows/block, 128 blocks, 128 threads. Whh fragments in registers.
// gin double-buffered via cp.async. Cell: exp-based sigmoids, tanh.approx.
// ---------------------------------------------------------------------------
#define LS_HP 68
#define LS_GP 264
#define LS_HSH  0
#define LS_GS   (16*LS_HP)
#define LS_GINB (LS_GS + 16*LS_GP)
#define LS_DONE (LS_GINB + 2*16*G_)
#define LS_SMEM (LS_DONE + T_*16)

__global__ __launch_bounds__(128, 1)
void k_lstm(const float* __restrict__ done,
            const float* __restrict__ h0, const float* __restrict__ c0,
            const float* __restrict__ Whh, float* __restrict__ out) {
    extern __shared__ float sm[];
    float* hsh    = sm + LS_HSH;
    float* gs     = sm + LS_GS;
    float* ginb   = sm + LS_GINB;
    float* done_s = sm + LS_DONE;

    const int tid  = threadIdx.x;
    const int lane = tid & 31;
    const int w    = tid >> 5;
    const int b0   = blockIdx.x * 16;
    const int qr   = lane >> 2, qc = lane & 3;

    // Whh fragments in registers: warp w owns gate cols [w*64, w*64+64)
    unsigned bf0[8][8], bf1[8][8];
    #pragma unroll
    for (int kt = 0; kt < 8; kt++)
        #pragma unroll
        for (int nt = 0; nt < 8; nt++) {
            int n = w*64 + nt*8 + qr, k = kt*8 + qc;
            bf0[kt][nt] = tf32_rna(Whh[n*H_ + k]);
            bf1[kt][nt] = tf32_rna(Whh[n*H_ + k + 4]);
        }

    for (int i = tid; i < T_*16; i += 128)
        done_s[i] = done[(i>>4)*B_ + b0 + (i&15)];

    const int rC = tid >> 3, u0 = (tid & 7) * 8;
    float c_reg[8];
    #pragma unroll
    for (int i = 0; i < 8; i++) {
        c_reg[i] = c0[(b0 + rC)*H_ + u0 + i];
        hsh[rC*LS_HP + u0 + i] = h0[(b0 + rC)*H_ + u0 + i];
    }

    // prologue: prefetch gin[t=0]
    {
        const float* src = g_gin + (size_t)b0 * G_;
        #pragma unroll
        for (int j = 0; j < 8; j++) {
            int q = tid + j*128;
            cp16(ginb + q*4, src + q*4);
        }
        asm volatile("cp.async.commit_group;");
    }
    __syncthreads();

    for (int t = 0; t < T_; t++) {
        // done-mask own slice
        float m = 1.0f - done_s[t*16 + rC];
        #pragma unroll
        for (int i = 0; i < 8; i++) c_reg[i] *= m;
        #pragma unroll
        for (int i = 0; i < 8; i++) hsh[rC*LS_HP + u0 + i] *= m;
        __syncthreads();

        // prefetch gin[t+1]
        if (t + 1 < T_) {
            float* dst = ginb + ((t+1)&1) * (16*G_);
            const float* src = g_gin + (size_t)((t+1)*B_ + b0) * G_;
            #pragma unroll
            for (int j = 0; j < 8; j++) {
                int q = tid + j*128;
                cp16(dst + q*4, src + q*4);
            }
            asm volatile("cp.async.commit_group;");
        }

        // gates_rec = h @ Whh^T  (m16 x n64 per warp, 1-term tf32)
        float acc[8][4];
        #pragma unroll
        for (int nt = 0; nt < 8; nt++)
            #pragma unroll
            for (int j = 0; j < 4; j++) acc[nt][j] = 0.f;

        #pragma unroll
        for (int kt = 0; kt < 8; kt++) {
            int k0 = kt*8;
            unsigned ahi[4];
            ahi[0] = tf32_rna(hsh[qr*LS_HP + k0 + qc]);
            ahi[1] = tf32_rna(hsh[(qr+8)*LS_HP + k0 + qc]);
            ahi[2] = tf32_rna(hsh[qr*LS_HP + k0 + qc + 4]);
            ahi[3] = tf32_rna(hsh[(qr+8)*LS_HP + k0 + qc + 4]);
            #pragma unroll
            for (int nt = 0; nt < 8; nt++)
                mma8(acc[nt], ahi, bf0[kt][nt], bf1[kt][nt]);
        }
        #pragma unroll
        for (int nt = 0; nt < 8; nt++) {
            int c = w*64 + nt*8 + 2*qc;
            *(float2*)&gs[qr*LS_GP + c]     = make_float2(acc[nt][0], acc[nt][1]);
            *(float2*)&gs[(qr+8)*LS_GP + c] = make_float2(acc[nt][2], acc[nt][3]);
        }

        if (t + 1 < T_) asm volatile("cp.async.wait_group 1;");
        else            asm volatile("cp.async.wait_group 0;");
        __syncthreads();

        // cell update (gate order i,f,g,o)
        const float* gv = ginb + (t&1)*(16*G_) + rC*G_;
        float hn[8];
        #pragma unroll
        for (int i = 0; i < 8; i++) {
            int u = u0 + i;
            float gi = gs[rC*LS_GP + u]        + gv[u];
            float gf = gs[rC*LS_GP + 64 + u]   + gv[64 + u];
            float gc = gs[rC*LS_GP + 128 + u]  + gv[128 + u];
            float go = gs[rC*LS_GP + 192 + u]  + gv[192 + u];
            float cn = fsig(gf)*c_reg[i] + fsig(gi)*ftanh_fast(gc);
            c_reg[i] = cn;
            hn[i] = fsig(go)*ftanh_fast(cn);
            hsh[rC*LS_HP + u] = hn[i];
        }
        float* zp = g_z + (size_t)(t*B_ + b0 + rC)*H_ + u0;
        ((float4*)zp)[0] = make_float4(hn[0], hn[1], hn[2], hn[3]);
        ((float4*)zp)[1] = make_float4(hn[4], hn[5], hn[6], hn[7]);
    }

    // epilogue: hT, cT (layout: logits | vf | hT | cT)
    const size_t OH = (size_t)TB_ * 16;
    #pragma unroll
    for (int i = 0; i < 8; i++) {
        out[OH + (size_t)(b0 + rC)*H_ + u0 + i]                 = hsh[rC*LS_HP + u0 + i];
        out[OH + (size_t)B_*H_ + (size_t)(b0 + rC)*H_ + u0 + i] = c_reg[i];
    }
}

// ---------------------------------------------------------------------------
// Kernel 3: actor/critic heads.
// ---------------------------------------------------------------------------
__global__ __launch_bounds__(128)
void k_heads(const float* __restrict__ Wa, const float* __restrict__ ba,
             const float* __restrict__ Wc, const float* __restrict__ bc,
             float* __restrict__ out) {
    __shared__ float ws[H_*16];
    __shared__ float zs[128*65];
    const int tid  = threadIdx.x;
    const int row0 = blockIdx.x * 128;

    for (int i = tid; i < 128*H_; i += 128) zs[(i>>6)*65 + (i&63)] = g_z[(size_t)row0*H_ + i];
    for (int i = tid; i < H_*16; i += 128) {
        int k = i >> 4, j = i & 15;
        ws[i] = (j < 15) ? Wa[k*A_ + j] : Wc[k];
    }
    __syncthreads();

    float acc[16];
    #pragma unroll
    for (int j = 0; j < 15; j++) acc[j] = ba[j];
    acc[15] = bc[0];
    #pragma unroll 4
    for (int k = 0; k < H_; k++) {
        float a = zs[tid*65 + k];
        #pragma unroll
        for (int j = 0; j < 16; j++) acc[j] = fmaf(a, ws[k*16 + j], acc[j]);
    }
    const size_t r = (size_t)row0 + tid;
    #pragma unroll
    for (int j = 0; j < 15; j++) out[r*A_ + j] = acc[j];
    out[(size_t)TB_*A_ + r] = acc[15];
}

// ---------------------------------------------------------------------------
extern "C" void kernel_launch(void* const* d_in, const int* in_sizes, int n_in,
                              void* d_out, int out_size) {
    const float* x    = (const float*)d_in[0];
    const float* done = (const float*)d_in[1];
    const float* h0   = (const float*)d_in[2];
    const float* c0   = (const float*)d_in[3];
    const float* W1   = (const float*)d_in[4];
    const float* b1   = (const float*)d_in[5];
    const float* W2   = (const float*)d_in[6];
    const float* b2   = (const float*)d_in[7];
    const float* Wih  = (const float*)d_in[8];
    const float* bih  = (const float*)d_in[9];
    const float* Whh  = (const float*)d_in[10];
    const float* bhh  = (const float*)d_in[11];
    const float* Wa   = (const float*)d_in[12];
    const float* ba   = (const float*)d_in[13];
    const float* Wc   = (const float*)d_in[14];
    const float* bc   = (const float*)d_in[15];
    float* out = (float*)d_out;

    cudaFuncSetAttribute(k_encode, cudaFuncAttributeMaxDynamicSharedMemorySize, ENC_SMEM*4);
    cudaFuncSetAttribute(k_lstm,   cudaFuncAttributeMaxDynamicSharedMemorySize, LS_SMEM*4);

    k_encode<<<TB_/128, 256, ENC_SMEM*4>>>(x, W1, b1, W2, b2, Wih, bih, bhh);
    k_lstm<<<B_/16, 128, LS_SMEM*4>>>(done, h0, c0, Whh, out);
    k_heads<<<TB_/128, 128>>>(Wa, ba, Wc, bc, out);
}

// round 5
// speedup vs baseline: 3.3595x; 1.3550x over previous
#include <cuda_runtime.h>

#define T_  128
#define B_  2048
#define F_  128
#define H_  64
#define A_  15
#define TB_ (T_*B_)
#define G_  256   // 4*H gates

// Scratch (allocation-free rule: __device__ globals)
__device__ float g_gin[(size_t)TB_ * G_];   // precomputed input-gate preactivations
__device__ float g_z[(size_t)TB_ * H_];     // LSTM hidden outputs per step

// ---------------------------------------------------------------------------
// math helpers
// ---------------------------------------------------------------------------
__device__ __forceinline__ float fsig(float x) {
    return __fdividef(1.0f, 1.0f + __expf(-x));
}
__device__ __forceinline__ float ftanh_fast(float x) {
    float y;
    asm("tanh.approx.f32 %0, %1;" : "=f"(y) : "f"(x));
    return y;
}
__device__ __forceinline__ unsigned tf32_rna(float x) {
    unsigned u; asm("cvt.rna.tf32.f32 %0, %1;" : "=r"(u) : "f"(x)); return u;
}
__device__ __forceinline__ float tf32f(float x) {
    return __uint_as_float(tf32_rna(x));
}
// d += a (m16k8, tf32) * b (k8n8, tf32)
__device__ __forceinline__ void mma8(float* d, const unsigned* a, unsigned b0, unsigned b1) {
    asm("mma.sync.aligned.m16n8k8.row.col.f32.tf32.tf32.f32 "
        "{%0,%1,%2,%3}, {%4,%5,%6,%7}, {%8,%9}, {%0,%1,%2,%3};"
        : "+f"(d[0]), "+f"(d[1]), "+f"(d[2]), "+f"(d[3])
        : "r"(a[0]), "r"(a[1]), "r"(a[2]), "r"(a[3]), "r"(b0), "r"(b1));
}
__device__ __forceinline__ void cp16(float* dst_smem, const float* src) {
    unsigned s = (unsigned)__cvta_generic_to_shared(dst_smem);
    asm volatile("cp.async.cg.shared.global [%0], [%1], 16;" :: "r"(s), "l"(src));
}
__device__ __forceinline__ void split2(float v, unsigned& hi, unsigned& lo) {
    hi = tf32_rna(v);
    lo = tf32_rna(v - __uint_as_float(hi));
}

// ---------------------------------------------------------------------------
// Kernel 1: fused MLP encoder + input-gate GEMM, tf32 mma (2-term A split).
// 256 threads (8 warps), 128 rows/block, 2048 blocks, 2 blocks/SM.
// smem (floats), 27520 total = 110080 B:
//   XS   0     : per-warp xs 2-buf [8w][2][16][36] = 9216 ; later ys [128][68]
//   WA   9216  : W1 tf32 [128][72] = 9216 ; later W2 tf32 [64][72] ;
//                later (with H1) raw Wih [256][68] = 17408 (spans 9216..26624)
//   H1   18432 : h1 [128][68] = 8704
//   BIAS 27136 : 384 (gin-bias 256 | b1 64 | b2 64)
// ---------------------------------------------------------------------------
#define ENC_XS   0
#define ENC_WA   9216
#define ENC_H1   18432
#define ENC_BIAS 27136
#define ENC_SMEM_F 27520

__global__ __launch_bounds__(256, 2)
void k_encode(const float* __restrict__ x,
              const float* __restrict__ W1, const float* __restrict__ b1,
              const float* __restrict__ W2, const float* __restrict__ b2,
              const float* __restrict__ Wih, const float* __restrict__ bih,
              const float* __restrict__ bhh) {
    extern __shared__ float sm[];
    float* wA   = sm + ENC_WA;
    float* h1   = sm + ENC_H1;
    float* ys   = sm + ENC_XS;     // reuses xs region after S1
    float* wg   = sm + ENC_WA;     // raw Wih after S2 (spans WA+H1)
    float* bias = sm + ENC_BIAS;

    const int tid  = threadIdx.x;
    const int lane = tid & 31;
    const int w    = tid >> 5;
    const int row0 = blockIdx.x * 128;
    const int qr   = lane >> 2;    // 0..7
    const int qc   = lane & 3;     // 0..3
    const int m0   = w * 16;       // warp's private row tile

    // per-warp xs double buffer: [2][16][36]
    float* xw = sm + ENC_XS + w * 1152;
    const float* xg = x + (size_t)(row0 + m0) * F_;

    // issue quarter loads q0,q1 (per-warp cp.async groups)
    #pragma unroll
    for (int q = 0; q < 2; q++) {
        float* dst = xw + q * 576;
        #pragma unroll
        for (int j = 0; j < 4; j++) {
            int idx = lane + j*32;           // float4 index 0..127
            int r = idx >> 3, c4 = (idx & 7) * 4;
            cp16(dst + r*36 + c4, xg + r*F_ + q*32 + c4);
        }
        asm volatile("cp.async.commit_group;");
    }

    // W1 (tf32-rounded) + biases
    for (int i = tid; i < F_*H_; i += 256) {
        int k = i >> 6, n = i & 63;
        wA[k*72 + n] = tf32f(W1[i]);
    }
    for (int i = tid; i < G_; i += 256) bias[i] = bih[i] + bhh[i];
    for (int i = tid; i < H_;  i += 256) { bias[256+i] = b1[i]; bias[320+i] = b2[i]; }
    __syncthreads();

    // ================= S1: h1 = tanh(x @ W1 + b1), K=128 =================
    {
        float acc[8][4];
        #pragma unroll
        for (int nt = 0; nt < 8; nt++)
            #pragma unroll
            for (int j = 0; j < 4; j++) acc[nt][j] = 0.f;

        #pragma unroll
        for (int q = 0; q < 4; q++) {
            if (q < 3) asm volatile("cp.async.wait_group 1;");
            else       asm volatile("cp.async.wait_group 0;");
            __syncwarp();
            float* xb = xw + (q & 1) * 576;
            #pragma unroll
            for (int kt2 = 0; kt2 < 4; kt2++) {
                int k0 = kt2 * 8;            // local col in quarter
                int bk = q*32 + k0 + qc;     // global k for B
                float a0 = xb[qr*36 + k0 + qc];
                float a1 = xb[(qr+8)*36 + k0 + qc];
                float a2 = xb[qr*36 + k0 + qc + 4];
                float a3 = xb[(qr+8)*36 + k0 + qc + 4];
                unsigned ahi[4], alo[4];
                split2(a0, ahi[0], alo[0]); split2(a1, ahi[1], alo[1]);
                split2(a2, ahi[2], alo[2]); split2(a3, ahi[3], alo[3]);
                #pragma unroll
                for (int nt = 0; nt < 8; nt++) {
                    int bn = nt*8 + qr;
                    unsigned bh0 = __float_as_uint(wA[bk*72 + bn]);
                    unsigned bh1 = __float_as_uint(wA[(bk+4)*72 + bn]);
                    mma8(acc[nt], ahi, bh0, bh1);
                    mma8(acc[nt], alo, bh0, bh1);
                }
            }
            __syncwarp();
            if (q < 2) {   // refill this buffer with quarter q+2
                float* dst = xw + (q & 1) * 576;
                #pragma unroll
                for (int j = 0; j < 4; j++) {
                    int idx = lane + j*32;
                    int r = idx >> 3, c4 = (idx & 7) * 4;
                    cp16(dst + r*36 + c4, xg + r*F_ + (q+2)*32 + c4);
                }
                asm volatile("cp.async.commit_group;");
            }
        }
        #pragma unroll
        for (int nt = 0; nt < 8; nt++) {
            int c = nt*8 + 2*qc;
            float bb0 = bias[256+c], bb1 = bias[256+c+1];
            *(float2*)&h1[(m0+qr)*68 + c] =
                make_float2(ftanh_fast(acc[nt][0]+bb0), ftanh_fast(acc[nt][1]+bb1));
            *(float2*)&h1[(m0+qr+8)*68 + c] =
                make_float2(ftanh_fast(acc[nt][2]+bb0), ftanh_fast(acc[nt][3]+bb1));
        }
    }
    __syncthreads();                    // all warps done with W1 region
    for (int i = tid; i < H_*H_; i += 256) {
        int k = i >> 6, n = i & 63;
        wA[k*72 + n] = tf32f(W2[i]);
    }
    __syncthreads();

    // ================= S2: ys = tanh(h1 @ W2 + b2), K=64 =================
    {
        float acc[8][4];
        #pragma unroll
        for (int nt = 0; nt < 8; nt++)
            #pragma unroll
            for (int j = 0; j < 4; j++) acc[nt][j] = 0.f;

        #pragma unroll 2
        for (int kt = 0; kt < 8; kt++) {
            int k0 = kt * 8;
            float a0 = h1[(m0+qr)*68 + k0 + qc];
            float a1 = h1[(m0+qr+8)*68 + k0 + qc];
            float a2 = h1[(m0+qr)*68 + k0 + qc + 4];
            float a3 = h1[(m0+qr+8)*68 + k0 + qc + 4];
            unsigned ahi[4], alo[4];
            split2(a0, ahi[0], alo[0]); split2(a1, ahi[1], alo[1]);
            split2(a2, ahi[2], alo[2]); split2(a3, ahi[3], alo[3]);
            #pragma unroll
            for (int nt = 0; nt < 8; nt++) {
                int bk = k0 + qc, bn = nt*8 + qr;
                unsigned bh0 = __float_as_uint(wA[bk*72 + bn]);
                unsigned bh1 = __float_as_uint(wA[(bk+4)*72 + bn]);
                mma8(acc[nt], ahi, bh0, bh1);
                mma8(acc[nt], alo, bh0, bh1);
            }
        }
        #pragma unroll
        for (int nt = 0; nt < 8; nt++) {
            int c = nt*8 + 2*qc;
            float bb0 = bias[320+c], bb1 = bias[320+c+1];
            *(float2*)&ys[(m0+qr)*68 + c] =
                make_float2(ftanh_fast(acc[nt][0]+bb0), ftanh_fast(acc[nt][1]+bb1));
            *(float2*)&ys[(m0+qr+8)*68 + c] =
                make_float2(ftanh_fast(acc[nt][2]+bb0), ftanh_fast(acc[nt][3]+bb1));
        }
    }
    __syncthreads();                    // W2 + h1 regions now dead everywhere

    // async-load FULL raw Wih [256][68] into dead WA+H1 regions
    #pragma unroll
    for (int j = 0; j < 16; j++) {
        int f = tid + j*256;            // 0..4095 (float4 units)
        int n = f >> 4, c4 = (f & 15) * 4;
        cp16(wg + n*68 + c4, Wih + n*H_ + c4);
    }
    asm volatile("cp.async.commit_group;");
    asm volatile("cp.async.wait_group 0;");
    __syncthreads();

    // ===== S3: gin = ys @ Wih^T + bias, K=64, N=256 (no syncs needed) =====
    #pragma unroll 1
    for (int ch = 0; ch < 4; ch++) {
        float acc[8][4];
        #pragma unroll
        for (int nt = 0; nt < 8; nt++)
            #pragma unroll
            for (int j = 0; j < 4; j++) acc[nt][j] = 0.f;

        #pragma unroll 2
        for (int kt = 0; kt < 8; kt++) {
            int k0 = kt * 8;
            float a0 = ys[(m0+qr)*68 + k0 + qc];
            float a1 = ys[(m0+qr+8)*68 + k0 + qc];
            float a2 = ys[(m0+qr)*68 + k0 + qc + 4];
            float a3 = ys[(m0+qr+8)*68 + k0 + qc + 4];
            unsigned ahi[4], alo[4];
            split2(a0, ahi[0], alo[0]); split2(a1, ahi[1], alo[1]);
            split2(a2, ahi[2], alo[2]); split2(a3, ahi[3], alo[3]);
            #pragma unroll
            for (int nt = 0; nt < 8; nt++) {
                int bn = ch*64 + nt*8 + qr, bk = k0 + qc;
                unsigned bh0 = tf32_rna(wg[bn*68 + bk]);
                unsigned bh1 = tf32_rna(wg[bn*68 + bk + 4]);
                mma8(acc[nt], ahi, bh0, bh1);
                mma8(acc[nt], alo, bh0, bh1);
            }
        }
        #pragma unroll
        for (int nt = 0; nt < 8; nt++) {
            int r = row0 + m0 + qr;
            int c = ch*64 + nt*8 + 2*qc;
            float bb0 = bias[c], bb1 = bias[c+1];
            *(float2*)&g_gin[(size_t)r*G_ + c] =
                make_float2(acc[nt][0] + bb0, acc[nt][1] + bb1);
            *(float2*)&g_gin[(size_t)(r+8)*G_ + c] =
                make_float2(acc[nt][2] + bb0, acc[nt][3] + bb1);
        }
    }
}

// ---------------------------------------------------------------------------
// Kernel 2: LSTM recurrence, tf32 mma (1-term h). 256 threads (8 warps),
// 16 batch rows/block, 128 blocks. Warp w computes gate cols [32w, 32w+32)
// with Whh fragments register-resident; cell update 4 units/thread.
// smem (floats): hsh [16][68] | gs [16][264] | ginb 2*4096 | done_s 2048
// ---------------------------------------------------------------------------
#define LS_HSH  0
#define LS_GS   1088
#define LS_GINB (LS_GS + 16*264)           // 5312
#define LS_DONE (LS_GINB + 2*16*G_)        // 13504
#define LS_SMEM_F (LS_DONE + T_*16)        // 15552

__global__ __launch_bounds__(256, 1)
void k_lstm(const float* __restrict__ done,
            const float* __restrict__ h0, const float* __restrict__ c0,
            const float* __restrict__ Whh, float* __restrict__ out) {
    extern __shared__ float sm[];
    float* hsh    = sm + LS_HSH;
    float* gs     = sm + LS_GS;
    float* ginb   = sm + LS_GINB;
    float* done_s = sm + LS_DONE;

    const int tid  = threadIdx.x;
    const int lane = tid & 31;
    const int w    = tid >> 5;
    const int b0   = blockIdx.x * 16;
    const int qr   = lane >> 2, qc = lane & 3;

    // Whh fragments: warp w owns gate cols [w*32, w*32+32)
    unsigned bf0[8][4], bf1[8][4];
    #pragma unroll
    for (int kt = 0; kt < 8; kt++)
        #pragma unroll
        for (int nt = 0; nt < 4; nt++) {
            int n = w*32 + nt*8 + qr, k = kt*8 + qc;
            bf0[kt][nt] = tf32_rna(Whh[n*H_ + k]);
            bf1[kt][nt] = tf32_rna(Whh[n*H_ + k + 4]);
        }

    for (int i = tid; i < T_*16; i += 256)
        done_s[i] = done[(i>>4)*B_ + b0 + (i&15)];

    // cell ownership: thread -> (row rC, units u0..u0+3)
    const int rC = tid >> 4, u0 = (tid & 15) * 4;
    float c_reg[4];
    #pragma unroll
    for (int i = 0; i < 4; i++) {
        c_reg[i] = c0[(b0 + rC)*H_ + u0 + i];
        hsh[rC*68 + u0 + i] = h0[(b0 + rC)*H_ + u0 + i];
    }

    // prologue: prefetch gin[t=0]
    {
        const float* src = g_gin + (size_t)b0 * G_;
        #pragma unroll
        for (int j = 0; j < 4; j++) {
            int q = tid + j*256;
            cp16(ginb + q*4, src + q*4);
        }
        asm volatile("cp.async.commit_group;");
    }
    __syncthreads();

    for (int t = 0; t < T_; t++) {
        // done-mask own slice
        float m = 1.0f - done_s[t*16 + rC];
        #pragma unroll
        for (int i = 0; i < 4; i++) c_reg[i] *= m;
        #pragma unroll
        for (int i = 0; i < 4; i++) hsh[rC*68 + u0 + i] *= m;
        __syncthreads();

        // prefetch gin[t+1]
        if (t + 1 < T_) {
            float* dst = ginb + ((t+1)&1) * (16*G_);
            const float* src = g_gin + (size_t)((t+1)*B_ + b0) * G_;
            #pragma unroll
            for (int j = 0; j < 4; j++) {
                int q = tid + j*256;
                cp16(dst + q*4, src + q*4);
            }
            asm volatile("cp.async.commit_group;");
        }

        // gates_rec = h @ Whh^T  (m16 x n32 per warp, 1-term tf32)
        float acc[4][4];
        #pragma unroll
        for (int nt = 0; nt < 4; nt++)
            #pragma unroll
            for (int j = 0; j < 4; j++) acc[nt][j] = 0.f;

        #pragma unroll
        for (int kt = 0; kt < 8; kt++) {
            int k0 = kt*8;
            unsigned ahi[4];
            ahi[0] = tf32_rna(hsh[qr*68 + k0 + qc]);
            ahi[1] = tf32_rna(hsh[(qr+8)*68 + k0 + qc]);
            ahi[2] = tf32_rna(hsh[qr*68 + k0 + qc + 4]);
            ahi[3] = tf32_rna(hsh[(qr+8)*68 + k0 + qc + 4]);
            #pragma unroll
            for (int nt = 0; nt < 4; nt++)
                mma8(acc[nt], ahi, bf0[kt][nt], bf1[kt][nt]);
        }
        #pragma unroll
        for (int nt = 0; nt < 4; nt++) {
            int c = w*32 + nt*8 + 2*qc;
            *(float2*)&gs[qr*264 + c]     = make_float2(acc[nt][0], acc[nt][1]);
            *(float2*)&gs[(qr+8)*264 + c] = make_float2(acc[nt][2], acc[nt][3]);
        }

        if (t + 1 < T_) asm volatile("cp.async.wait_group 1;");
        else            asm volatile("cp.async.wait_group 0;");
        __syncthreads();

        // cell update (gate order i,f,g,o)
        const float* gv = ginb + (t&1)*(16*G_) + rC*G_;
        float hn[4];
        #pragma unroll
        for (int i = 0; i < 4; i++) {
            int u = u0 + i;
            float gi = gs[rC*264 + u]        + gv[u];
            float gf = gs[rC*264 + 64 + u]   + gv[64 + u];
            float gc = gs[rC*264 + 128 + u]  + gv[128 + u];
            float go = gs[rC*264 + 192 + u]  + gv[192 + u];
            float cn = fsig(gf)*c_reg[i] + fsig(gi)*ftanh_fast(gc);
            c_reg[i] = cn;
            hn[i] = fsig(go)*ftanh_fast(cn);
            hsh[rC*68 + u] = hn[i];
        }
        float* zp = g_z + (size_t)(t*B_ + b0 + rC)*H_ + u0;
        *(float4*)zp = make_float4(hn[0], hn[1], hn[2], hn[3]);
    }

    // epilogue: hT, cT (layout: logits | vf | hT | cT)
    const size_t OH = (size_t)TB_ * 16;
    #pragma unroll
    for (int i = 0; i < 4; i++) {
        out[OH + (size_t)(b0 + rC)*H_ + u0 + i]                 = hsh[rC*68 + u0 + i];
        out[OH + (size_t)B_*H_ + (size_t)(b0 + rC)*H_ + u0 + i] = c_reg[i];
    }
}

// ---------------------------------------------------------------------------
// Kernel 3: actor/critic heads.
// ---------------------------------------------------------------------------
__global__ __launch_bounds__(128)
void k_heads(const float* __restrict__ Wa, const float* __restrict__ ba,
             const float* __restrict__ Wc, const float* __restrict__ bc,
             float* __restrict__ out) {
    __shared__ float ws[H_*16];
    __shared__ float zs[128*65];
    const int tid  = threadIdx.x;
    const int row0 = blockIdx.x * 128;

    for (int i = tid; i < 128*H_; i += 128) zs[(i>>6)*65 + (i&63)] = g_z[(size_t)row0*H_ + i];
    for (int i = tid; i < H_*16; i += 128) {
        int k = i >> 4, j = i & 15;
        ws[i] = (j < 15) ? Wa[k*A_ + j] : Wc[k];
    }
    __syncthreads();

    float acc[16];
    #pragma unroll
    for (int j = 0; j < 15; j++) acc[j] = ba[j];
    acc[15] = bc[0];
    #pragma unroll 4
    for (int k = 0; k < H_; k++) {
        float a = zs[tid*65 + k];
        #pragma unroll
        for (int j = 0; j < 16; j++) acc[j] = fmaf(a, ws[k*16 + j], acc[j]);
    }
    const size_t r = (size_t)row0 + tid;
    #pragma unroll
    for (int j = 0; j < 15; j++) out[r*A_ + j] = acc[j];
    out[(size_t)TB_*A_ + r] = acc[15];
}

// ---------------------------------------------------------------------------
extern "C" void kernel_launch(void* const* d_in, const int* in_sizes, int n_in,
                              void* d_out, int out_size) {
    const float* x    = (const float*)d_in[0];
    const float* done = (const float*)d_in[1];
    const float* h0   = (const float*)d_in[2];
    const float* c0   = (const float*)d_in[3];
    const float* W1   = (const float*)d_in[4];
    const float* b1   = (const float*)d_in[5];
    const float* W2   = (const float*)d_in[6];
    const float* b2   = (const float*)d_in[7];
    const float* Wih  = (const float*)d_in[8];
    const float* bih  = (const float*)d_in[9];
    const float* Whh  = (const float*)d_in[10];
    const float* bhh  = (const float*)d_in[11];
    const float* Wa   = (const float*)d_in[12];
    const float* ba   = (const float*)d_in[13];
    const float* Wc   = (const float*)d_in[14];
    const float* bc   = (const float*)d_in[15];
    float* out = (float*)d_out;

    cudaFuncSetAttribute(k_encode, cudaFuncAttributeMaxDynamicSharedMemorySize, ENC_SMEM_F*4);
    cudaFuncSetAttribute(k_lstm,   cudaFuncAttributeMaxDynamicSharedMemorySize, LS_SMEM_F*4);

    k_encode<<<TB_/128, 256, ENC_SMEM_F*4>>>(x, W1, b1, W2, b2, Wih, bih, bhh);
    k_lstm<<<B_/16, 256, LS_SMEM_F*4>>>(done, h0, c0, Whh, out);
    k_heads<<<TB_/128, 128>>>(Wa, ba, Wc, bc, out);
}

// round 6
// speedup vs baseline: 3.9562x; 1.1776x over previous
#include <cuda_runtime.h>

#define T_  128
#define B_  2048
#define F_  128
#define H_  64
#define A_  15
#define TB_ (T_*B_)
#define G_  256   // 4*H gates

// Scratch (allocation-free rule: __device__ globals)
__device__ float g_gin[(size_t)TB_ * G_];   // precomputed input-gate preactivations
__device__ float g_z[(size_t)TB_ * H_];     // LSTM hidden outputs per step

// ---------------------------------------------------------------------------
// math helpers
// ---------------------------------------------------------------------------
__device__ __forceinline__ float fsig(float x) {
    return __fdividef(1.0f, 1.0f + __expf(-x));
}
__device__ __forceinline__ float ftanh_fast(float x) {
    float y;
    asm("tanh.approx.f32 %0, %1;" : "=f"(y) : "f"(x));
    return y;
}
__device__ __forceinline__ unsigned tf32_rna(float x) {
    unsigned u; asm("cvt.rna.tf32.f32 %0, %1;" : "=r"(u) : "f"(x)); return u;
}
__device__ __forceinline__ float tf32f(float x) {
    return __uint_as_float(tf32_rna(x));
}
// d += a (m16k8, tf32) * b (k8n8, tf32)
__device__ __forceinline__ void mma8(float* d, const unsigned* a, unsigned b0, unsigned b1) {
    asm("mma.sync.aligned.m16n8k8.row.col.f32.tf32.tf32.f32 "
        "{%0,%1,%2,%3}, {%4,%5,%6,%7}, {%8,%9}, {%0,%1,%2,%3};"
        : "+f"(d[0]), "+f"(d[1]), "+f"(d[2]), "+f"(d[3])
        : "r"(a[0]), "r"(a[1]), "r"(a[2]), "r"(a[3]), "r"(b0), "r"(b1));
}
__device__ __forceinline__ void cp16(float* dst_smem, const float* src) {
    unsigned s = (unsigned)__cvta_generic_to_shared(dst_smem);
    asm volatile("cp.async.cg.shared.global [%0], [%1], 16;" :: "r"(s), "l"(src));
}
__device__ __forceinline__ void split2(float v, unsigned& hi, unsigned& lo) {
    hi = tf32_rna(v);
    lo = tf32_rna(v - __uint_as_float(hi));
}

// ---------------------------------------------------------------------------
// Kernel 1: fused MLP encoder + input-gate GEMM, tf32 mma.
// S1/S2: 2-term A split. S3: 1-term (ys and Wih pre-rounded in smem, zero cvt).
// 256 threads (8 warps), 128 rows/block, 2048 blocks, 2 blocks/SM.
// ---------------------------------------------------------------------------
#define ENC_XS   0
#define ENC_WA   9216
#define ENC_H1   18432
#define ENC_BIAS 27136
#define ENC_SMEM_F 27520

__global__ __launch_bounds__(256, 2)
void k_encode(const float* __restrict__ x,
              const float* __restrict__ W1, const float* __restrict__ b1,
              const float* __restrict__ W2, const float* __restrict__ b2,
              const float* __restrict__ Wih, const float* __restrict__ bih,
              const float* __restrict__ bhh) {
    extern __shared__ float sm[];
    float* wA   = sm + ENC_WA;
    float* h1   = sm + ENC_H1;
    float* ys   = sm + ENC_XS;     // reuses xs region after S1
    float* wg   = sm + ENC_WA;     // raw->rounded Wih after S2 (spans WA+H1)
    float* bias = sm + ENC_BIAS;

    const int tid  = threadIdx.x;
    const int lane = tid & 31;
    const int w    = tid >> 5;
    const int row0 = blockIdx.x * 128;
    const int qr   = lane >> 2;    // 0..7
    const int qc   = lane & 3;     // 0..3
    const int m0   = w * 16;       // warp's private row tile

    // per-warp xs double buffer: [2][16][36]
    float* xw = sm + ENC_XS + w * 1152;
    const float* xg = x + (size_t)(row0 + m0) * F_;

    // issue quarter loads q0,q1 (per-warp cp.async groups)
    #pragma unroll
    for (int q = 0; q < 2; q++) {
        float* dst = xw + q * 576;
        #pragma unroll
        for (int j = 0; j < 4; j++) {
            int idx = lane + j*32;           // float4 index 0..127
            int r = idx >> 3, c4 = (idx & 7) * 4;
            cp16(dst + r*36 + c4, xg + r*F_ + q*32 + c4);
        }
        asm volatile("cp.async.commit_group;");
    }

    // W1 (tf32-rounded) + biases
    for (int i = tid; i < F_*H_; i += 256) {
        int k = i >> 6, n = i & 63;
        wA[k*72 + n] = tf32f(W1[i]);
    }
    for (int i = tid; i < G_; i += 256) bias[i] = bih[i] + bhh[i];
    for (int i = tid; i < H_;  i += 256) { bias[256+i] = b1[i]; bias[320+i] = b2[i]; }
    __syncthreads();

    // ================= S1: h1 = tanh(x @ W1 + b1), K=128, 2-term =========
    {
        float acc[8][4];
        #pragma unroll
        for (int nt = 0; nt < 8; nt++)
            #pragma unroll
            for (int j = 0; j < 4; j++) acc[nt][j] = 0.f;

        #pragma unroll
        for (int q = 0; q < 4; q++) {
            if (q < 3) asm volatile("cp.async.wait_group 1;");
            else       asm volatile("cp.async.wait_group 0;");
            __syncwarp();
            float* xb = xw + (q & 1) * 576;
            #pragma unroll
            for (int kt2 = 0; kt2 < 4; kt2++) {
                int k0 = kt2 * 8;            // local col in quarter
                int bk = q*32 + k0 + qc;     // global k for B
                float a0 = xb[qr*36 + k0 + qc];
                float a1 = xb[(qr+8)*36 + k0 + qc];
                float a2 = xb[qr*36 + k0 + qc + 4];
                float a3 = xb[(qr+8)*36 + k0 + qc + 4];
                unsigned ahi[4], alo[4];
                split2(a0, ahi[0], alo[0]); split2(a1, ahi[1], alo[1]);
                split2(a2, ahi[2], alo[2]); split2(a3, ahi[3], alo[3]);
                #pragma unroll
                for (int nt = 0; nt < 8; nt++) {
                    int bn = nt*8 + qr;
                    unsigned bh0 = __float_as_uint(wA[bk*72 + bn]);
                    unsigned bh1 = __float_as_uint(wA[(bk+4)*72 + bn]);
                    mma8(acc[nt], ahi, bh0, bh1);
                    mma8(acc[nt], alo, bh0, bh1);
                }
            }
            __syncwarp();
            if (q < 2) {   // refill this buffer with quarter q+2
                float* dst = xw + (q & 1) * 576;
                #pragma unroll
                for (int j = 0; j < 4; j++) {
                    int idx = lane + j*32;
                    int r = idx >> 3, c4 = (idx & 7) * 4;
                    cp16(dst + r*36 + c4, xg + r*F_ + (q+2)*32 + c4);
                }
                asm volatile("cp.async.commit_group;");
            }
        }
        #pragma unroll
        for (int nt = 0; nt < 8; nt++) {
            int c = nt*8 + 2*qc;
            float bb0 = bias[256+c], bb1 = bias[256+c+1];
            *(float2*)&h1[(m0+qr)*68 + c] =
                make_float2(ftanh_fast(acc[nt][0]+bb0), ftanh_fast(acc[nt][1]+bb1));
            *(float2*)&h1[(m0+qr+8)*68 + c] =
                make_float2(ftanh_fast(acc[nt][2]+bb0), ftanh_fast(acc[nt][3]+bb1));
        }
    }
    __syncthreads();                    // all warps done with W1 region
    for (int i = tid; i < H_*H_; i += 256) {
        int k = i >> 6, n = i & 63;
        wA[k*72 + n] = tf32f(W2[i]);
    }
    __syncthreads();

    // ========= S2: ys = tf32(tanh(h1 @ W2 + b2)), K=64, 2-term ===========
    {
        float acc[8][4];
        #pragma unroll
        for (int nt = 0; nt < 8; nt++)
            #pragma unroll
            for (int j = 0; j < 4; j++) acc[nt][j] = 0.f;

        #pragma unroll 2
        for (int kt = 0; kt < 8; kt++) {
            int k0 = kt * 8;
            float a0 = h1[(m0+qr)*68 + k0 + qc];
            float a1 = h1[(m0+qr+8)*68 + k0 + qc];
            float a2 = h1[(m0+qr)*68 + k0 + qc + 4];
            float a3 = h1[(m0+qr+8)*68 + k0 + qc + 4];
            unsigned ahi[4], alo[4];
            split2(a0, ahi[0], alo[0]); split2(a1, ahi[1], alo[1]);
            split2(a2, ahi[2], alo[2]); split2(a3, ahi[3], alo[3]);
            #pragma unroll
            for (int nt = 0; nt < 8; nt++) {
                int bk = k0 + qc, bn = nt*8 + qr;
                unsigned bh0 = __float_as_uint(wA[bk*72 + bn]);
                unsigned bh1 = __float_as_uint(wA[(bk+4)*72 + bn]);
                mma8(acc[nt], ahi, bh0, bh1);
                mma8(acc[nt], alo, bh0, bh1);
            }
        }
        // store ys PRE-ROUNDED to tf32 (S3 is 1-term; loads need no cvt)
        #pragma unroll
        for (int nt = 0; nt < 8; nt++) {
            int c = nt*8 + 2*qc;
            float bb0 = bias[320+c], bb1 = bias[320+c+1];
            *(float2*)&ys[(m0+qr)*68 + c] =
                make_float2(tf32f(ftanh_fast(acc[nt][0]+bb0)),
                            tf32f(ftanh_fast(acc[nt][1]+bb1)));
            *(float2*)&ys[(m0+qr+8)*68 + c] =
                make_float2(tf32f(ftanh_fast(acc[nt][2]+bb0)),
                            tf32f(ftanh_fast(acc[nt][3]+bb1)));
        }
    }
    __syncthreads();                    // W2 + h1 regions now dead everywhere

    // async-load FULL raw Wih [256][68] into dead WA+H1 regions,
    // then round own elements in place (no cvt needed in S3).
    #pragma unroll
    for (int j = 0; j < 16; j++) {
        int f = tid + j*256;            // 0..4095 (float4 units)
        int n = f >> 4, c4 = (f & 15) * 4;
        cp16(wg + n*68 + c4, Wih + n*H_ + c4);
    }
    asm volatile("cp.async.commit_group;");
    asm volatile("cp.async.wait_group 0;");
    #pragma unroll
    for (int j = 0; j < 16; j++) {
        int f = tid + j*256;
        int n = f >> 4, c4 = (f & 15) * 4;
        float* p = wg + n*68 + c4;
        p[0] = tf32f(p[0]); p[1] = tf32f(p[1]);
        p[2] = tf32f(p[2]); p[3] = tf32f(p[3]);
    }
    __syncthreads();

    // ===== S3: gin = ys @ Wih^T + bias, K=64, N=256, 1-term, zero cvt ====
    #pragma unroll 1
    for (int ch = 0; ch < 4; ch++) {
        float acc[8][4];
        #pragma unroll
        for (int nt = 0; nt < 8; nt++)
            #pragma unroll
            for (int j = 0; j < 4; j++) acc[nt][j] = 0.f;

        #pragma unroll 2
        for (int kt = 0; kt < 8; kt++) {
            int k0 = kt * 8;
            unsigned a[4];
            a[0] = __float_as_uint(ys[(m0+qr)*68 + k0 + qc]);
            a[1] = __float_as_uint(ys[(m0+qr+8)*68 + k0 + qc]);
            a[2] = __float_as_uint(ys[(m0+qr)*68 + k0 + qc + 4]);
            a[3] = __float_as_uint(ys[(m0+qr+8)*68 + k0 + qc + 4]);
            #pragma unroll
            for (int nt = 0; nt < 8; nt++) {
                int bn = ch*64 + nt*8 + qr, bk = k0 + qc;
                mma8(acc[nt], a,
                     __float_as_uint(wg[bn*68 + bk]),
                     __float_as_uint(wg[bn*68 + bk + 4]));
            }
        }
        #pragma unroll
        for (int nt = 0; nt < 8; nt++) {
            int r = row0 + m0 + qr;
            int c = ch*64 + nt*8 + 2*qc;
            float bb0 = bias[c], bb1 = bias[c+1];
            *(float2*)&g_gin[(size_t)r*G_ + c] =
                make_float2(acc[nt][0] + bb0, acc[nt][1] + bb1);
            *(float2*)&g_gin[(size_t)(r+8)*G_ + c] =
                make_float2(acc[nt][2] + bb0, acc[nt][3] + bb1);
        }
    }
}

// ---------------------------------------------------------------------------
// Kernel 2: LSTM recurrence, tf32 mma (1-term h). 256 threads (8 warps),
// 16 batch rows/block, 128 blocks. hsh stored PRE-ROUNDED tf32 and
// PRE-MASKED for the upcoming step -> gates MMA does raw loads, no cvt,
// no mask phase. Cell reads gates/gin as float4.
// ---------------------------------------------------------------------------
#define LS_HSH  0
#define LS_GS   1088
#define LS_GINB (LS_GS + 16*264)           // 5312
#define LS_DONE (LS_GINB + 2*16*G_)        // 13504
#define LS_SMEM_F (LS_DONE + T_*16)        // 15552

__global__ __launch_bounds__(256, 1)
void k_lstm(const float* __restrict__ done,
            const float* __restrict__ h0, const float* __restrict__ c0,
            const float* __restrict__ Whh, float* __restrict__ out) {
    extern __shared__ float sm[];
    float* hsh    = sm + LS_HSH;
    float* gs     = sm + LS_GS;
    float* ginb   = sm + LS_GINB;
    float* done_s = sm + LS_DONE;

    const int tid  = threadIdx.x;
    const int lane = tid & 31;
    const int w    = tid >> 5;
    const int b0   = blockIdx.x * 16;
    const int qr   = lane >> 2, qc = lane & 3;

    // Whh fragments: warp w owns gate cols [w*32, w*32+32)
    unsigned bf0[8][4], bf1[8][4];
    #pragma unroll
    for (int kt = 0; kt < 8; kt++)
        #pragma unroll
        for (int nt = 0; nt < 4; nt++) {
            int n = w*32 + nt*8 + qr, k = kt*8 + qc;
            bf0[kt][nt] = tf32_rna(Whh[n*H_ + k]);
            bf1[kt][nt] = tf32_rna(Whh[n*H_ + k + 4]);
        }

    for (int i = tid; i < T_*16; i += 256)
        done_s[i] = done[(i>>4)*B_ + b0 + (i&15)];

    // cell ownership: thread -> (row rC, units u0..u0+3)
    const int rC = tid >> 4, u0 = (tid & 15) * 4;
    const float mk0 = 1.0f - done[b0 + rC];     // step-0 mask, direct gmem
    float c_reg[4], hlast[4];
    #pragma unroll
    for (int i = 0; i < 4; i++) {
        c_reg[i] = c0[(b0 + rC)*H_ + u0 + i] * mk0;
        hsh[rC*68 + u0 + i] = tf32f(h0[(b0 + rC)*H_ + u0 + i]) * mk0;
        hlast[i] = 0.f;
    }

    // prologue: prefetch gin[t=0]
    {
        const float* src = g_gin + (size_t)b0 * G_;
        #pragma unroll
        for (int j = 0; j < 4; j++) {
            int q = tid + j*256;
            cp16(ginb + q*4, src + q*4);
        }
        asm volatile("cp.async.commit_group;");
    }
    __syncthreads();

    for (int t = 0; t < T_; t++) {
        // prefetch gin[t+1] (buffer's prior readers finished before the
        // trailing sync of step t-1)
        if (t + 1 < T_) {
            float* dst = ginb + ((t+1)&1) * (16*G_);
            const float* src = g_gin + (size_t)((t+1)*B_ + b0) * G_;
            #pragma unroll
            for (int j = 0; j < 4; j++) {
                int q = tid + j*256;
                cp16(dst + q*4, src + q*4);
            }
            asm volatile("cp.async.commit_group;");
        }

        // gates_rec = h @ Whh^T  (m16 x n32 per warp; hsh pre-rounded+masked)
        float acc[4][4];
        #pragma unroll
        for (int nt = 0; nt < 4; nt++)
            #pragma unroll
            for (int j = 0; j < 4; j++) acc[nt][j] = 0.f;

        #pragma unroll
        for (int kt = 0; kt < 8; kt++) {
            int k0 = kt*8;
            unsigned a[4];
            a[0] = __float_as_uint(hsh[qr*68 + k0 + qc]);
            a[1] = __float_as_uint(hsh[(qr+8)*68 + k0 + qc]);
            a[2] = __float_as_uint(hsh[qr*68 + k0 + qc + 4]);
            a[3] = __float_as_uint(hsh[(qr+8)*68 + k0 + qc + 4]);
            #pragma unroll
            for (int nt = 0; nt < 4; nt++)
                mma8(acc[nt], a, bf0[kt][nt], bf1[kt][nt]);
        }
        #pragma unroll
        for (int nt = 0; nt < 4; nt++) {
            int c = w*32 + nt*8 + 2*qc;
            *(float2*)&gs[qr*264 + c]     = make_float2(acc[nt][0], acc[nt][1]);
            *(float2*)&gs[(qr+8)*264 + c] = make_float2(acc[nt][2], acc[nt][3]);
        }

        if (t + 1 < T_) asm volatile("cp.async.wait_group 1;");
        else            asm volatile("cp.async.wait_group 0;");
        __syncthreads();

        // cell update (gate order i,f,g,o); float4 gate loads
        const float* gv = ginb + (t&1)*(16*G_) + rC*G_;
        float mn = 1.0f;
        if (t + 1 < T_) mn = 1.0f - done_s[(t+1)*16 + rC];

        float4 gi4 = *(const float4*)&gs[rC*264 + u0];
        float4 gf4 = *(const float4*)&gs[rC*264 + 64 + u0];
        float4 gg4 = *(const float4*)&gs[rC*264 + 128 + u0];
        float4 go4 = *(const float4*)&gs[rC*264 + 192 + u0];
        float4 vi4 = *(const float4*)&gv[u0];
        float4 vf4 = *(const float4*)&gv[64 + u0];
        float4 vg4 = *(const float4*)&gv[128 + u0];
        float4 vo4 = *(const float4*)&gv[192 + u0];

        float gi[4] = {gi4.x+vi4.x, gi4.y+vi4.y, gi4.z+vi4.z, gi4.w+vi4.w};
        float gf[4] = {gf4.x+vf4.x, gf4.y+vf4.y, gf4.z+vf4.z, gf4.w+vf4.w};
        float gg[4] = {gg4.x+vg4.x, gg4.y+vg4.y, gg4.z+vg4.z, gg4.w+vg4.w};
        float go[4] = {go4.x+vo4.x, go4.y+vo4.y, go4.z+vo4.z, go4.w+vo4.w};

        float hn[4], hr[4];
        #pragma unroll
        for (int i = 0; i < 4; i++) {
            float cn = fsig(gf[i])*c_reg[i] + fsig(gi[i])*ftanh_fast(gg[i]);
            hn[i] = fsig(go[i])*ftanh_fast(cn);
            c_reg[i] = cn * mn;                 // pre-mask for next step
            hr[i] = tf32f(hn[i]) * mn;          // pre-round + pre-mask
            hlast[i] = hn[i];
        }
        *(float4*)&g_z[(size_t)(t*B_ + b0 + rC)*H_ + u0] =
            make_float4(hn[0], hn[1], hn[2], hn[3]);
        *(float4*)&hsh[rC*68 + u0] = make_float4(hr[0], hr[1], hr[2], hr[3]);
        __syncthreads();
    }

    // epilogue: hT, cT (layout: logits | vf | hT | cT), full precision
    const size_t OH = (size_t)TB_ * 16;
    #pragma unroll
    for (int i = 0; i < 4; i++) {
        out[OH + (size_t)(b0 + rC)*H_ + u0 + i]                 = hlast[i];
        out[OH + (size_t)B_*H_ + (size_t)(b0 + rC)*H_ + u0 + i] = c_reg[i];
    }
}

// ---------------------------------------------------------------------------
// Kernel 3: actor/critic heads.
// ---------------------------------------------------------------------------
__global__ __launch_bounds__(128)
void k_heads(const float* __restrict__ Wa, const float* __restrict__ ba,
             const float* __restrict__ Wc, const float* __restrict__ bc,
             float* __restrict__ out) {
    __shared__ float ws[H_*16];
    __shared__ float zs[128*65];
    const int tid  = threadIdx.x;
    const int row0 = blockIdx.x * 128;

    for (int i = tid; i < 128*H_; i += 128) zs[(i>>6)*65 + (i&63)] = g_z[(size_t)row0*H_ + i];
    for (int i = tid; i < H_*16; i += 128) {
        int k = i >> 4, j = i & 15;
        ws[i] = (j < 15) ? Wa[k*A_ + j] : Wc[k];
    }
    __syncthreads();

    float acc[16];
    #pragma unroll
    for (int j = 0; j < 15; j++) acc[j] = ba[j];
    acc[15] = bc[0];
    #pragma unroll 4
    for (int k = 0; k < H_; k++) {
        float a = zs[tid*65 + k];
        #pragma unroll
        for (int j = 0; j < 16; j++) acc[j] = fmaf(a, ws[k*16 + j], acc[j]);
    }
    const size_t r = (size_t)row0 + tid;
    #pragma unroll
    for (int j = 0; j < 15; j++) out[r*A_ + j] = acc[j];
    out[(size_t)TB_*A_ + r] = acc[15];
}

// ---------------------------------------------------------------------------
extern "C" void kernel_launch(void* const* d_in, const int* in_sizes, int n_in,
                              void* d_out, int out_size) {
    const float* x    = (const float*)d_in[0];
    const float* done = (const float*)d_in[1];
    const float* h0   = (const float*)d_in[2];
    const float* c0   = (const float*)d_in[3];
    const float* W1   = (const float*)d_in[4];
    const float* b1   = (const float*)d_in[5];
    const float* W2   = (const float*)d_in[6];
    const float* b2   = (const float*)d_in[7];
    const float* Wih  = (const float*)d_in[8];
    const float* bih  = (const float*)d_in[9];
    const float* Whh  = (const float*)d_in[10];
    const float* bhh  = (const float*)d_in[11];
    const float* Wa   = (const float*)d_in[12];
    const float* ba   = (const float*)d_in[13];
    const float* Wc   = (const float*)d_in[14];
    const float* bc   = (const float*)d_in[15];
    float* out = (float*)d_out;

    cudaFuncSetAttribute(k_encode, cudaFuncAttributeMaxDynamicSharedMemorySize, ENC_SMEM_F*4);
    cudaFuncSetAttribute(k_lstm,   cudaFuncAttributeMaxDynamicSharedMemorySize, LS_SMEM_F*4);

    k_encode<<<TB_/128, 256, ENC_SMEM_F*4>>>(x, W1, b1, W2, b2, Wih, bih, bhh);
    k_lstm<<<B_/16, 256, LS_SMEM_F*4>>>(done, h0, c0, Whh, out);
    k_heads<<<TB_/128, 128>>>(Wa, ba, Wc, bc, out);
}